// round 15
// baseline (speedup 1.0000x reference)
#include <cuda_runtime.h>
#include <cstdint>

#define BDIM 64        // 8 element-slots x 8 c-threads; 8 elems per thread => 64 elems/CTA

// ---------------- packed-weight scratch (device globals; no allocation) ----------------
__device__ __align__(16) float g_W1[72 * 32];   // [j][i]: cols 0..31 s, 32..39 a, 40..71 h
__device__ __align__(16) float g_F1[32 * 32];   // [j][i] = fc1_w[i][j]
__device__ __align__(16) float g_MW[32 * 32];   // [j][i] = mean_w[i][j]
__device__ __align__(16) float g_SW[32 * 32];   // [j][i] = std_w[i][j]
__device__ __align__(16) float g_b1[32];
__device__ __align__(16) float g_fb[32];
__device__ __align__(16) float g_mb[32];
__device__ __align__(16) float g_sb[32];

__global__ void pack_kernel(const float* __restrict__ W_ih, const float* __restrict__ W_hh,
                            const float* __restrict__ b_ih, const float* __restrict__ b_hh,
                            const float* __restrict__ fc1_w, const float* __restrict__ fc1_b,
                            const float* __restrict__ mean_w, const float* __restrict__ mean_b,
                            const float* __restrict__ std_w, const float* __restrict__ std_b) {
    int t = threadIdx.x;
    for (int idx = t; idx < 72 * 32; idx += blockDim.x) {
        int j = idx >> 5, i = idx & 31;
        g_W1[idx] = (j < 40) ? W_ih[i * 40 + j] : W_hh[i * 32 + (j - 40)];
    }
    for (int idx = t; idx < 32 * 32; idx += blockDim.x) {
        int j = idx >> 5, i = idx & 31;
        g_F1[idx] = fc1_w[i * 32 + j];
        g_MW[idx] = mean_w[i * 32 + j];
        g_SW[idx] = std_w[i * 32 + j];
    }
    if (t < 32) {
        g_b1[t] = b_ih[t] + b_hh[t];
        g_fb[t] = fc1_b[t];
        g_mb[t] = mean_b[t];
        g_sb[t] = std_b[t];
    }
}

// ---------------- f32x2 helpers (by-value, named scalars only) ----------------
__device__ __forceinline__ unsigned long long pk(float x) {
    unsigned long long r;
    asm("mov.b64 %0, {%1, %1};" : "=l"(r) : "f"(x));
    return r;
}
__device__ __forceinline__ float2 up(unsigned long long v) {
    float2 f;
    asm("mov.b64 {%0, %1}, %2;" : "=f"(f.x), "=f"(f.y) : "l"(v));
    return f;
}
#define FMA2(acc, w, x) asm("fma.rn.f32x2 %0, %1, %2, %0;" : "+l"(acc) : "l"(w), "l"(x))

// ---------------- activations ----------------
__device__ __forceinline__ float fast_tanh(float x) {
    x = fminf(fmaxf(x, -15.f), 15.f);
    float e = __expf(2.f * x);
    return __fdividef(e - 1.f, e + 1.f);
}
__device__ __forceinline__ float fast_elu(float x) {
    return x > 0.f ? x : (__expf(x) - 1.f);
}
__device__ __forceinline__ float softplus_eps(float x) {
    float ax = fabsf(x);
    return fmaxf(x, 0.f) + __logf(1.f + __expf(-ax)) + 1e-5f;
}

#define EACH8(M) M(0) M(1) M(2) M(3) M(4) M(5) M(6) M(7)

// ---------------- main rollout kernel: 8 threads/elem x 8 elems/thread ----------------
__global__ __launch_bounds__(BDIM) void rssm_kernel(
    const float* __restrict__ s0, const float* __restrict__ h0,
    const float* __restrict__ actions, float* __restrict__ out,
    int B, int T, int nsteps)
{
    __shared__ __align__(16) float sW1[72 * 32];
    __shared__ __align__(16) float sF1[32 * 32];
    __shared__ __align__(16) float sMW[32 * 32];
    __shared__ __align__(16) float sSW[32 * 32];
    __shared__ __align__(16) float sb1[32];
    __shared__ __align__(16) float sfb[32];
    __shared__ __align__(16) float smb[32];
    __shared__ __align__(16) float ssb[32];
    // per-element state, [elem 0..63][32 floats]
    __shared__ __align__(16) float sS[64 * 32];
    __shared__ __align__(16) float sH[64 * 32];
    __shared__ __align__(16) float sHid[64 * 32];
    __shared__ __align__(16) float sA[64 * 8];   // staged actions for current t

    {
        int t0 = threadIdx.x;
        for (int i = t0; i < 72 * 32; i += BDIM) sW1[i] = g_W1[i];
        for (int i = t0; i < 32 * 32; i += BDIM) {
            sF1[i] = g_F1[i];
            sMW[i] = g_MW[i];
            sSW[i] = g_SW[i];
        }
        if (t0 < 32) {
            sb1[t0] = g_b1[t0];
            sfb[t0] = g_fb[t0];
            smb[t0] = g_mb[t0];
            ssb[t0] = g_sb[t0];
        }
    }

    const int tid = threadIdx.x;
    const int c = tid & 7;          // output slice [4c, 4c+4)
    const int e = tid >> 3;         // element slot 0..7; thread's elems: e + 8*i
    const int b0 = blockIdx.x * 64; // CTA's first element

    float4* sSv   = (float4*)sS;    // [elem][8]
    float4* sHv   = (float4*)sH;
    float4* sHidv = (float4*)sHid;
    float4* sAv   = (float4*)sA;    // [elem][2]

    // seed state: thread writes its c-slice of its 8 elements
#pragma unroll
    for (int i = 0; i < 8; i++) {
        int el = e + 8 * i;
        int b  = b0 + el;
        sSv[el * 8 + c] = ((const float4*)(s0 + (size_t)b * 32))[c];
        sHv[el * 8 + c] = ((const float4*)(h0 + (size_t)b * 32))[c];
    }
    __syncthreads();

    const ulonglong2* W1u = (const ulonglong2*)sW1;
    const ulonglong2* F1u = (const ulonglong2*)sF1;
    const ulonglong2* MWu = (const ulonglong2*)sMW;
    const ulonglong2* SWu = (const ulonglong2*)sSW;
    const ulonglong2 b1u = ((const ulonglong2*)sb1)[c];
    const ulonglong2 fbu = ((const ulonglong2*)sfb)[c];
    const ulonglong2 mbu = ((const ulonglong2*)smb)[c];
    const ulonglong2 sbu = ((const ulonglong2*)ssb)[c];

    // action staging assignment: warp-local lane -> one of the warp's 32 elements
    const int L = tid & 31, wp = tid >> 5;
    const int stage_el = (wp * 4 + (L & 3)) + 8 * (L >> 2);
    const float4* stage_act = (const float4*)(actions + (size_t)(b0 + stage_el) * T * 8);

// generic GEMM block over 4 columns jb*4..jb*4+3 with per-elem x from ADDR (uses i, jb)
#define COLSTEP(i) { unsigned long long _xx = pk(xs[(i) * 4 + jj]); \
                     FMA2(p0_##i, _w.x, _xx); FMA2(p1_##i, _w.y, _xx); }
#define GBLK(Wu, COLBASE, ADDR)                                     \
    do {                                                            \
        float xs[32];                                               \
        _Pragma("unroll")                                           \
        for (int i = 0; i < 8; i++) {                               \
            float4 v = (ADDR);                                      \
            xs[i*4+0]=v.x; xs[i*4+1]=v.y; xs[i*4+2]=v.z; xs[i*4+3]=v.w; \
        }                                                           \
        _Pragma("unroll")                                           \
        for (int jj = 0; jj < 4; jj++) {                            \
            ulonglong2 _w = (Wu)[((COLBASE) + jb * 4 + jj) * 8 + c];\
            EACH8(COLSTEP)                                          \
        }                                                           \
    } while (0)

#define COLMS(i) { unsigned long long _xx = pk(xs[(i) * 4 + jj]); \
                   FMA2(m0_##i, _mw.x, _xx); FMA2(m1_##i, _mw.y, _xx); \
                   FMA2(q0_##i, _qw.x, _xx); FMA2(q1_##i, _qw.y, _xx); }
#define GBLKMS(ADDR)                                                \
    do {                                                            \
        float xs[32];                                               \
        _Pragma("unroll")                                           \
        for (int i = 0; i < 8; i++) {                               \
            float4 v = (ADDR);                                      \
            xs[i*4+0]=v.x; xs[i*4+1]=v.y; xs[i*4+2]=v.z; xs[i*4+3]=v.w; \
        }                                                           \
        _Pragma("unroll")                                           \
        for (int jj = 0; jj < 4; jj++) {                            \
            ulonglong2 _mw = MWu[(jb * 4 + jj) * 8 + c];            \
            ulonglong2 _qw = SWu[(jb * 4 + jj) * 8 + c];            \
            EACH8(COLMS)                                            \
        }                                                           \
    } while (0)

#pragma unroll 1
    for (int t = 0; t < nsteps; t++) {
        // ---- stage actions for this step (1 lane : 1 element) ----
        {
            float4 a0 = stage_act[2 * t], a1 = stage_act[2 * t + 1];
            sAv[stage_el * 2]     = a0;
            sAv[stage_el * 2 + 1] = a1;
        }
        __syncwarp();

        // ================= GEMM1: h_pre = W1 @ [s | a | h] + b1 =================
#define DECLP(i) unsigned long long p0_##i = b1u.x, p1_##i = b1u.y;
        EACH8(DECLP)
#pragma unroll
        for (int jb = 0; jb < 8; jb++) GBLK(W1u, 0,  sSv[e * 8 + 64 * i + jb]);
#pragma unroll
        for (int jb = 0; jb < 2; jb++) GBLK(W1u, 32, sAv[e * 2 + 16 * i + jb]);
#pragma unroll
        for (int jb = 0; jb < 8; jb++) GBLK(W1u, 40, sHv[e * 8 + 64 * i + jb]);
        __syncwarp();   // all reads of sS/sA/sH done before overwriting sH
#define WRITEH(i) { float2 u0 = up(p0_##i), u1 = up(p1_##i); \
                    sHv[(e + 8 * (i)) * 8 + c] = make_float4(fast_tanh(u0.x), fast_tanh(u0.y), \
                                                             fast_tanh(u1.x), fast_tanh(u1.y)); }
        EACH8(WRITEH)
        __syncwarp();

        // ================= GEMM2: hid = elu(F1 @ h + fb) =================
#define REINITP(i) p0_##i = fbu.x; p1_##i = fbu.y;
        EACH8(REINITP)
#pragma unroll
        for (int jb = 0; jb < 8; jb++) GBLK(F1u, 0, sHv[e * 8 + 64 * i + jb]);
#define WRITEHID(i) { float2 u0 = up(p0_##i), u1 = up(p1_##i); \
                      sHidv[(e + 8 * (i)) * 8 + c] = make_float4(fast_elu(u0.x), fast_elu(u0.y), \
                                                                 fast_elu(u1.x), fast_elu(u1.y)); }
        EACH8(WRITEHID)
        __syncwarp();

        // ================= GEMM3: fused mean + std =================
#define DECLM(i) unsigned long long m0_##i = mbu.x, m1_##i = mbu.y, \
                                    q0_##i = sbu.x, q1_##i = sbu.y;
        EACH8(DECLM)
#pragma unroll
        for (int jb = 0; jb < 8; jb++) GBLKMS(sHidv[e * 8 + 64 * i + jb]);

        // ---- epilogue: s <- mean; out[t][b] = [mean | softplus(std)+eps] ----
        float* outt = out + (size_t)t * (size_t)B * 64;
#define EPI(i) { int _el = e + 8 * (i);                                          \
                 float4* _o4 = (float4*)(outt + (size_t)(b0 + _el) * 64);        \
                 float2 u0 = up(m0_##i), u1 = up(m1_##i);                        \
                 float4 mv = make_float4(u0.x, u0.y, u1.x, u1.y);                \
                 _o4[c] = mv; sSv[_el * 8 + c] = mv;                             \
                 float2 v0 = up(q0_##i), v1 = up(q1_##i);                        \
                 _o4[8 + c] = make_float4(softplus_eps(v0.x), softplus_eps(v0.y),\
                                          softplus_eps(v1.x), softplus_eps(v1.y)); }
        EACH8(EPI)
        __syncwarp();   // sS/sA visible & read-complete before next step
    }
}

// ---------------- entry point ----------------
extern "C" void kernel_launch(void* const* d_in, const int* in_sizes, int n_in,
                              void* d_out, int out_size) {
    const float* s0      = (const float*)d_in[0];
    const float* h0      = (const float*)d_in[1];
    const float* actions = (const float*)d_in[2];
    const float* W_ih    = (const float*)d_in[3];
    const float* W_hh    = (const float*)d_in[4];
    const float* b_ih    = (const float*)d_in[5];
    const float* b_hh    = (const float*)d_in[6];
    const float* fc1_w   = (const float*)d_in[7];
    const float* fc1_b   = (const float*)d_in[8];
    const float* mean_w  = (const float*)d_in[9];
    const float* mean_b  = (const float*)d_in[10];
    const float* std_w   = (const float*)d_in[11];
    const float* std_b   = (const float*)d_in[12];

    int B = in_sizes[0] / 32;                 // s0 is [B, 32]
    int T = in_sizes[2] / (B * 8);            // actions is [B, T, 8]
    int nsteps = out_size / (B * 64);         // out is [nsteps, B, 64]

    pack_kernel<<<1, 256>>>(W_ih, W_hh, b_ih, b_hh, fc1_w, fc1_b,
                            mean_w, mean_b, std_w, std_b);
    rssm_kernel<<<B / 64, BDIM>>>(s0, h0, actions, (float*)d_out, B, T, nsteps);
}